// round 9
// baseline (speedup 1.0000x reference)
#include <cuda_runtime.h>
#include <math.h>

// Problem shape
#define HDIM     4096
#define EDIM     64
#define M_TOTAL  16384

// Tiling: grid 128 (1 CTA/SM), 512 threads (16 warps -> 4/SMSP for latency hiding)
#define BM        128               // rows per CTA
#define KT        32                // K-tile
#define NT        (HDIM / KT)       // 128 K-tiles
#define NTHREADS  512

__global__ __launch_bounds__(NTHREADS, 1)
void router_kernel(const float* __restrict__ x,
                   const float* __restrict__ w,
                   float* __restrict__ out)
{
    // XOR-swizzled tiles (no padding): element (kk, r) lives at [kk][r ^ ((kk>>2 & 7)<<2)].
    // STS transpose is bank-conflict-free (verified bijection per warp);
    // LDS of aligned 4-row groups stays contiguous (XOR only touches bits [2:5)).
    __shared__ union {
        struct {
            float xs[KT][BM];      // 16 KB
            float ws[KT][EDIM];    //  8 KB
        } t;
        float ls[BM][EDIM + 4];    // epilogue logits tile (stride 68)
    } sm;

    const int tid = threadIdx.x;
    const int m0  = blockIdx.x * BM;

    // compute mapping: thread tile = 4 rows x 4 experts
    const int eg = tid & 15;           // experts 4*eg .. 4*eg+3
    const int rg = tid >> 4;           // rows    4*rg .. 4*rg+3   (0..31)

    // x global-load mapping: 2 float4 per thread per tile (rows r0, r0+64)
    const int xk4 = tid & 7;           // float4 index in K within tile (0..7)
    const int xr0 = tid >> 3;          // row 0..63

    // w global-load mapping: 1 float4 per thread per tile (512 = 64 experts x 8 k4)
    const int wk4 = tid & 7;
    const int we  = tid >> 3;          // expert 0..63

    // swizzle constant on the store side: c = 4*k4 (same for all 4 components)
    const int xsw = 4 * xk4;
    const int wsw = 4 * wk4;

    // accumulators: acc[row_pair][expert], packed f32x2 over (row, row+1)
    unsigned long long acc[2][4];
    #pragma unroll
    for (int i = 0; i < 2; i++)
        #pragma unroll
        for (int j = 0; j < 4; j++)
            acc[i][j] = 0ull;

    float4 xv[2], wv;

    // prefetch tile 0 into registers
    {
        const float* xp = x + (size_t)m0 * HDIM + 4 * xk4;
        xv[0] = *(const float4*)(xp + (size_t)xr0 * HDIM);
        xv[1] = *(const float4*)(xp + (size_t)(xr0 + 64) * HDIM);
        wv    = *(const float4*)(w + (size_t)we * HDIM + 4 * wk4);
    }

    for (int t = 0; t < NT; t++) {
        // ---- store prefetched tile to smem (swizzled transpose, conflict-free) ----
        #pragma unroll
        for (int i = 0; i < 2; i++) {
            int rs = (xr0 + 64 * i) ^ xsw;
            sm.t.xs[4 * xk4 + 0][rs] = xv[i].x;
            sm.t.xs[4 * xk4 + 1][rs] = xv[i].y;
            sm.t.xs[4 * xk4 + 2][rs] = xv[i].z;
            sm.t.xs[4 * xk4 + 3][rs] = xv[i].w;
        }
        {
            int es = we ^ wsw;
            sm.t.ws[4 * wk4 + 0][es] = wv.x;
            sm.t.ws[4 * wk4 + 1][es] = wv.y;
            sm.t.ws[4 * wk4 + 2][es] = wv.z;
            sm.t.ws[4 * wk4 + 3][es] = wv.w;
        }
        __syncthreads();

        // ---- prefetch next tile (overlaps with compute below) ----
        if (t + 1 < NT) {
            const int k0 = (t + 1) * KT;
            const float* xp = x + (size_t)m0 * HDIM + k0 + 4 * xk4;
            xv[0] = *(const float4*)(xp + (size_t)xr0 * HDIM);
            xv[1] = *(const float4*)(xp + (size_t)(xr0 + 64) * HDIM);
            wv    = *(const float4*)(w + (size_t)we * HDIM + k0 + 4 * wk4);
        }

        // ---- mainloop: 32 kk steps, 8 fma.rn.f32x2 each ----
        #pragma unroll
        for (int kk = 0; kk < KT; kk++) {
            const int c = ((kk >> 2) & 7) << 2;     // compile-time per unrolled kk
            ulonglong2 xa = *(const ulonglong2*)&sm.t.xs[kk][(4 * rg) ^ c];
            float4 wf = *(const float4*)&sm.t.ws[kk][(4 * eg) ^ c];

            unsigned long long xr[2];
            xr[0] = xa.x; xr[1] = xa.y;

            unsigned long long wd[4];
            asm("mov.b64 %0, {%1,%1};" : "=l"(wd[0]) : "r"(__float_as_uint(wf.x)));
            asm("mov.b64 %0, {%1,%1};" : "=l"(wd[1]) : "r"(__float_as_uint(wf.y)));
            asm("mov.b64 %0, {%1,%1};" : "=l"(wd[2]) : "r"(__float_as_uint(wf.z)));
            asm("mov.b64 %0, {%1,%1};" : "=l"(wd[3]) : "r"(__float_as_uint(wf.w)));

            #pragma unroll
            for (int rp = 0; rp < 2; rp++)
                #pragma unroll
                for (int e = 0; e < 4; e++)
                    asm("fma.rn.f32x2 %0, %1, %2, %0;"
                        : "+l"(acc[rp][e])
                        : "l"(xr[rp]), "l"(wd[e]));
        }
        __syncthreads();
    }

    // ---- epilogue ----
    float* logits_out = out;
    float* idx_out    = out + (size_t)M_TOTAL * EDIM;
    float* p_out      = idx_out + (size_t)M_TOTAL * 2;

    // rows here are UNswizzled — mainloop done, smem repurposed
    #pragma unroll
    for (int rp = 0; rp < 2; rp++) {
        #pragma unroll
        for (int e = 0; e < 4; e++) {
            unsigned int lo, hi;
            asm("mov.b64 {%0,%1}, %2;" : "=r"(lo), "=r"(hi) : "l"(acc[rp][e]));
            int r   = 4 * rg + 2 * rp;
            int col = 4 * eg + e;
            sm.ls[r][col]     = __uint_as_float(lo);
            sm.ls[r + 1][col] = __uint_as_float(hi);
        }
    }
    __syncthreads();

    // coalesced logits store: 4 x float4 per thread
    #pragma unroll
    for (int q = 0; q < 4; q++) {
        int idx = tid + NTHREADS * q;       // 0..2047 float4 slots
        int row = idx >> 4;
        int c4  = idx & 15;
        float4 v = *(const float4*)&sm.ls[row][c4 * 4];
        *(float4*)&logits_out[(size_t)(m0 + row) * EDIM + c4 * 4] = v;
    }

    // one thread per row: stable top-2 (strict >, ties -> lower index = lax.top_k)
    if (tid < BM) {
        const float* r = &sm.ls[tid][0];
        float best = -INFINITY, sec = -INFINITY;
        int bi = 0, si = 0;
        #pragma unroll 8
        for (int i = 0; i < EDIM; i++) {
            float v = r[i];
            if (v > best) { sec = best; si = bi; best = v; bi = i; }
            else if (v > sec) { sec = v; si = i; }
        }
        float tt  = expf(sec - best);
        float inv = 1.0f / (1.0f + tt);
        size_t m = (size_t)(m0 + tid);
        idx_out[m * 2 + 0] = (float)bi;
        idx_out[m * 2 + 1] = (float)si;
        p_out[m * 2 + 0]   = inv;
        p_out[m * 2 + 1]   = tt * inv;
    }
}

extern "C" void kernel_launch(void* const* d_in, const int* in_sizes, int n_in,
                              void* d_out, int out_size)
{
    const float* x  = (const float*)d_in[0];
    const float* gw = (const float*)d_in[1];
    // defensive: identify tensors by size (x = 67108864, gate_w = 262144)
    if (n_in >= 2 && in_sizes[0] < in_sizes[1]) {
        const float* tmp = x; x = gw; gw = tmp;
    }
    router_kernel<<<M_TOTAL / BM, NTHREADS>>>(x, gw, (float*)d_out);
}

// round 11
// speedup vs baseline: 1.2871x; 1.2871x over previous
#include <cuda_runtime.h>
#include <math.h>

// Problem shape
#define HDIM     4096
#define EDIM     64
#define M_TOTAL  16384

// Tiling: grid 128 (1 CTA/SM), 256 threads, 8x4 thread tile (proven best core),
// double-buffered smem -> ONE barrier per tile.
#define BM        128
#define KT        32
#define NT        (HDIM / KT)       // 128 K-tiles
#define NTHREADS  256

__global__ __launch_bounds__(NTHREADS, 1)
void router_kernel(const float* __restrict__ x,
                   const float* __restrict__ w,
                   float* __restrict__ out)
{
    // XOR-swizzled tiles (no padding): element (kk, r) lives at [kk][r ^ ((kk>>2 & 7)<<2)].
    // STS transpose is bank-conflict-free; LDS of aligned 4-row groups stays contiguous.
    __shared__ union {
        struct {
            float xs[2][KT][BM];     // 32 KB (double-buffered)
            float ws[2][KT][EDIM];   // 16 KB
        } t;
        float ls[BM][EDIM + 4];      // epilogue logits tile (stride 68)
    } sm;

    const int tid = threadIdx.x;
    const int m0  = blockIdx.x * BM;

    // compute mapping: thread tile = 8 rows x 4 experts
    const int eg = tid & 15;           // experts 4*eg .. 4*eg+3
    const int rg = tid >> 4;           // rows    8*rg .. 8*rg+7

    // x global-load mapping: 4 float4 per thread per tile
    const int xk4   = tid & 7;         // float4 index in K within tile (0..7)
    const int xrow0 = tid >> 3;        // row 0..31, +32*i

    // w global-load mapping: 2 float4 per thread per tile
    const int wk4 = tid & 7;
    const int we0 = tid >> 3;          // expert 0..31, +32*i

    // swizzle constants for the store side: c = 4*k4 (same for all 4 components)
    const int xsw = 4 * xk4;
    const int wsw = 4 * wk4;

    // accumulators: acc[row_pair][expert], packed f32x2 over (row, row+1)
    unsigned long long acc[4][4];
    #pragma unroll
    for (int i = 0; i < 4; i++)
        #pragma unroll
        for (int j = 0; j < 4; j++)
            acc[i][j] = 0ull;

    float4 xv[4], wv[2];

    // ---- prologue: load tile 0 -> buffer 0 ----
    {
        const float* xp = x + (size_t)m0 * HDIM + 4 * xk4;
        #pragma unroll
        for (int i = 0; i < 4; i++)
            xv[i] = *(const float4*)(xp + (size_t)(xrow0 + 32 * i) * HDIM);
        const float* wp = w + 4 * wk4;
        #pragma unroll
        for (int i = 0; i < 2; i++)
            wv[i] = *(const float4*)(wp + (size_t)(we0 + 32 * i) * HDIM);

        #pragma unroll
        for (int i = 0; i < 4; i++) {
            int rs = (xrow0 + 32 * i) ^ xsw;
            sm.t.xs[0][4 * xk4 + 0][rs] = xv[i].x;
            sm.t.xs[0][4 * xk4 + 1][rs] = xv[i].y;
            sm.t.xs[0][4 * xk4 + 2][rs] = xv[i].z;
            sm.t.xs[0][4 * xk4 + 3][rs] = xv[i].w;
        }
        #pragma unroll
        for (int i = 0; i < 2; i++) {
            int es = (we0 + 32 * i) ^ wsw;
            sm.t.ws[0][4 * wk4 + 0][es] = wv[i].x;
            sm.t.ws[0][4 * wk4 + 1][es] = wv[i].y;
            sm.t.ws[0][4 * wk4 + 2][es] = wv[i].z;
            sm.t.ws[0][4 * wk4 + 3][es] = wv[i].w;
        }
    }
    __syncthreads();

    // ---- mainloop: ONE barrier per tile (double buffering) ----
    for (int t = 0; t < NT; t++) {
        const int cb = t & 1;

        // prefetch next tile FIRST (max DRAM overlap with the compute below)
        if (t + 1 < NT) {
            const int k0 = (t + 1) * KT;
            const float* xp = x + (size_t)m0 * HDIM + k0 + 4 * xk4;
            #pragma unroll
            for (int i = 0; i < 4; i++)
                xv[i] = *(const float4*)(xp + (size_t)(xrow0 + 32 * i) * HDIM);
            const float* wp = w + k0 + 4 * wk4;
            #pragma unroll
            for (int i = 0; i < 2; i++)
                wv[i] = *(const float4*)(wp + (size_t)(we0 + 32 * i) * HDIM);
        }

        // compute from buffer cb: 32 kk steps, 16 fma.rn.f32x2 each
        #pragma unroll
        for (int kk = 0; kk < KT; kk++) {
            const int c  = ((kk >> 2) & 7) << 2;    // compile-time per unrolled kk
            const int r1 = (8 * rg) ^ c;
            const int r2 = r1 ^ 4;
            ulonglong2 xa = *(const ulonglong2*)&sm.t.xs[cb][kk][r1];
            ulonglong2 xb = *(const ulonglong2*)&sm.t.xs[cb][kk][r2];
            float4 wf = *(const float4*)&sm.t.ws[cb][kk][(4 * eg) ^ c];

            unsigned long long xr[4];
            xr[0] = xa.x; xr[1] = xa.y; xr[2] = xb.x; xr[3] = xb.y;

            unsigned long long wd[4];
            asm("mov.b64 %0, {%1,%1};" : "=l"(wd[0]) : "r"(__float_as_uint(wf.x)));
            asm("mov.b64 %0, {%1,%1};" : "=l"(wd[1]) : "r"(__float_as_uint(wf.y)));
            asm("mov.b64 %0, {%1,%1};" : "=l"(wd[2]) : "r"(__float_as_uint(wf.z)));
            asm("mov.b64 %0, {%1,%1};" : "=l"(wd[3]) : "r"(__float_as_uint(wf.w)));

            #pragma unroll
            for (int rp = 0; rp < 4; rp++)
                #pragma unroll
                for (int e = 0; e < 4; e++)
                    asm("fma.rn.f32x2 %0, %1, %2, %0;"
                        : "+l"(acc[rp][e])
                        : "l"(xr[rp]), "l"(wd[e]));
        }

        // store prefetched tile into the other buffer (its readers all passed
        // the barrier at the end of iteration t-1 — safe)
        if (t + 1 < NT) {
            const int nb = cb ^ 1;
            #pragma unroll
            for (int i = 0; i < 4; i++) {
                int rs = (xrow0 + 32 * i) ^ xsw;
                sm.t.xs[nb][4 * xk4 + 0][rs] = xv[i].x;
                sm.t.xs[nb][4 * xk4 + 1][rs] = xv[i].y;
                sm.t.xs[nb][4 * xk4 + 2][rs] = xv[i].z;
                sm.t.xs[nb][4 * xk4 + 3][rs] = xv[i].w;
            }
            #pragma unroll
            for (int i = 0; i < 2; i++) {
                int es = (we0 + 32 * i) ^ wsw;
                sm.t.ws[nb][4 * wk4 + 0][es] = wv[i].x;
                sm.t.ws[nb][4 * wk4 + 1][es] = wv[i].y;
                sm.t.ws[nb][4 * wk4 + 2][es] = wv[i].z;
                sm.t.ws[nb][4 * wk4 + 3][es] = wv[i].w;
            }
        }
        __syncthreads();
    }

    // ---- epilogue ----
    float* logits_out = out;
    float* idx_out    = out + (size_t)M_TOTAL * EDIM;
    float* p_out      = idx_out + (size_t)M_TOTAL * 2;

    // rows here are UNswizzled — mainloop done (barrier above), smem repurposed
    #pragma unroll
    for (int rp = 0; rp < 4; rp++) {
        #pragma unroll
        for (int e = 0; e < 4; e++) {
            unsigned int lo, hi;
            asm("mov.b64 {%0,%1}, %2;" : "=r"(lo), "=r"(hi) : "l"(acc[rp][e]));
            int r   = 8 * rg + 2 * rp;
            int col = 4 * eg + e;
            sm.ls[r][col]     = __uint_as_float(lo);
            sm.ls[r + 1][col] = __uint_as_float(hi);
        }
    }
    __syncthreads();

    // coalesced logits store: 8 x float4 per thread
    #pragma unroll
    for (int q = 0; q < 8; q++) {
        int idx = tid + NTHREADS * q;       // 0..2047 float4 slots
        int row = idx >> 4;
        int c4  = idx & 15;
        float4 v = *(const float4*)&sm.ls[row][c4 * 4];
        *(float4*)&logits_out[(size_t)(m0 + row) * EDIM + c4 * 4] = v;
    }

    // one thread per row: stable top-2 (strict >, ties -> lower index = lax.top_k)
    if (tid < BM) {
        const float* r = &sm.ls[tid][0];
        float best = -INFINITY, sec = -INFINITY;
        int bi = 0, si = 0;
        #pragma unroll 8
        for (int i = 0; i < EDIM; i++) {
            float v = r[i];
            if (v > best) { sec = best; si = bi; best = v; bi = i; }
            else if (v > sec) { sec = v; si = i; }
        }
        float tt  = expf(sec - best);
        float inv = 1.0f / (1.0f + tt);
        size_t m = (size_t)(m0 + tid);
        idx_out[m * 2 + 0] = (float)bi;
        idx_out[m * 2 + 1] = (float)si;
        p_out[m * 2 + 0]   = inv;
        p_out[m * 2 + 1]   = tt * inv;
    }
}

extern "C" void kernel_launch(void* const* d_in, const int* in_sizes, int n_in,
                              void* d_out, int out_size)
{
    const float* x  = (const float*)d_in[0];
    const float* gw = (const float*)d_in[1];
    // defensive: identify tensors by size (x = 67108864, gate_w = 262144)
    if (n_in >= 2 && in_sizes[0] < in_sizes[1]) {
        const float* tmp = x; x = gw; gw = tmp;
    }
    router_kernel<<<M_TOTAL / BM, NTHREADS>>>(x, gw, (float*)d_out);
}

// round 13
// speedup vs baseline: 1.3194x; 1.0251x over previous
#include <cuda_runtime.h>
#include <math.h>

// Problem shape
#define HDIM     4096
#define EDIM     64
#define M_TOTAL  16384

// Tiling: grid 128 (1 CTA/SM), 256 threads, 8x4 thread tile (proven best core),
// single-buffer R8 skeleton + explicit software-pipelined kk loop.
#define BM        128
#define KT        32
#define NT        (HDIM / KT)       // 128 K-tiles
#define NTHREADS  256

__global__ __launch_bounds__(NTHREADS, 1)
void router_kernel(const float* __restrict__ x,
                   const float* __restrict__ w,
                   float* __restrict__ out)
{
    // XOR-swizzled tiles (no padding): element (kk, r) lives at [kk][r ^ ((kk>>2 & 7)<<2)].
    // STS transpose is bank-conflict-free; LDS of aligned 4-row groups stays contiguous.
    __shared__ union {
        struct {
            float xs[KT][BM];      // 16 KB
            float ws[KT][EDIM];    //  8 KB
        } t;
        float ls[BM][EDIM + 4];    // epilogue logits tile (stride 68)
    } sm;

    const int tid = threadIdx.x;
    const int m0  = blockIdx.x * BM;

    // compute mapping: thread tile = 8 rows x 4 experts
    const int eg = tid & 15;           // experts 4*eg .. 4*eg+3
    const int rg = tid >> 4;           // rows    8*rg .. 8*rg+7

    // x global-load mapping: 4 float4 per thread per tile
    const int xk4   = tid & 7;         // float4 index in K within tile (0..7)
    const int xrow0 = tid >> 3;        // row 0..31, +32*i

    // w global-load mapping: 2 float4 per thread per tile
    const int wk4 = tid & 7;
    const int we0 = tid >> 3;          // expert 0..31, +32*i

    // swizzle constants for the store side: c = 4*k4 (same for all 4 components)
    const int xsw = 4 * xk4;
    const int wsw = 4 * wk4;

    // accumulators: acc[row_pair][expert], packed f32x2 over (row, row+1)
    unsigned long long acc[4][4];
    #pragma unroll
    for (int i = 0; i < 4; i++)
        #pragma unroll
        for (int j = 0; j < 4; j++)
            acc[i][j] = 0ull;

    float4 xv[4], wv[2];

    // prefetch tile 0 into registers
    {
        const float* xp = x + (size_t)m0 * HDIM + 4 * xk4;
        #pragma unroll
        for (int i = 0; i < 4; i++)
            xv[i] = *(const float4*)(xp + (size_t)(xrow0 + 32 * i) * HDIM);
        const float* wp = w + 4 * wk4;
        #pragma unroll
        for (int i = 0; i < 2; i++)
            wv[i] = *(const float4*)(wp + (size_t)(we0 + 32 * i) * HDIM);
    }

    for (int t = 0; t < NT; t++) {
        // ---- store prefetched tile to smem (swizzled transpose, conflict-free) ----
        #pragma unroll
        for (int i = 0; i < 4; i++) {
            int rs = (xrow0 + 32 * i) ^ xsw;
            sm.t.xs[4 * xk4 + 0][rs] = xv[i].x;
            sm.t.xs[4 * xk4 + 1][rs] = xv[i].y;
            sm.t.xs[4 * xk4 + 2][rs] = xv[i].z;
            sm.t.xs[4 * xk4 + 3][rs] = xv[i].w;
        }
        #pragma unroll
        for (int i = 0; i < 2; i++) {
            int es = (we0 + 32 * i) ^ wsw;
            sm.t.ws[4 * wk4 + 0][es] = wv[i].x;
            sm.t.ws[4 * wk4 + 1][es] = wv[i].y;
            sm.t.ws[4 * wk4 + 2][es] = wv[i].z;
            sm.t.ws[4 * wk4 + 3][es] = wv[i].w;
        }
        __syncthreads();

        // ---- prefetch next GLOBAL tile (overlaps with the whole compute phase) ----
        if (t + 1 < NT) {
            const int k0 = (t + 1) * KT;
            const float* xp = x + (size_t)m0 * HDIM + k0 + 4 * xk4;
            #pragma unroll
            for (int i = 0; i < 4; i++)
                xv[i] = *(const float4*)(xp + (size_t)(xrow0 + 32 * i) * HDIM);
            const float* wp = w + k0 + 4 * wk4;
            #pragma unroll
            for (int i = 0; i < 2; i++)
                wv[i] = *(const float4*)(wp + (size_t)(we0 + 32 * i) * HDIM);
        }

        // ---- software-pipelined mainloop: LDS for kk+1 issued before FMAs of kk ----
        ulonglong2 xa, xb;
        float4 wf;
        {
            const int c0 = 0;
            const int r1 = (8 * rg) ^ c0;
            xa = *(const ulonglong2*)&sm.t.xs[0][r1];
            xb = *(const ulonglong2*)&sm.t.xs[0][r1 ^ 4];
            wf = *(const float4*)&sm.t.ws[0][(4 * eg) ^ c0];
        }

        #pragma unroll
        for (int kk = 0; kk < KT; kk++) {
            // 1) issue next iteration's LDS first (hidden under this kk's FMAs)
            ulonglong2 nxa = xa, nxb = xb;
            float4 nwf = wf;
            if (kk + 1 < KT) {
                const int cn  = (((kk + 1) >> 2) & 7) << 2;   // compile-time
                const int rn1 = (8 * rg) ^ cn;
                nxa = *(const ulonglong2*)&sm.t.xs[kk + 1][rn1];
                nxb = *(const ulonglong2*)&sm.t.xs[kk + 1][rn1 ^ 4];
                nwf = *(const float4*)&sm.t.ws[kk + 1][(4 * eg) ^ cn];
            }

            // 2) duplicate w (operands loaded a full iteration ago -> no wait)
            unsigned long long wd[4];
            asm("mov.b64 %0, {%1,%1};" : "=l"(wd[0]) : "r"(__float_as_uint(wf.x)));
            asm("mov.b64 %0, {%1,%1};" : "=l"(wd[1]) : "r"(__float_as_uint(wf.y)));
            asm("mov.b64 %0, {%1,%1};" : "=l"(wd[2]) : "r"(__float_as_uint(wf.z)));
            asm("mov.b64 %0, {%1,%1};" : "=l"(wd[3]) : "r"(__float_as_uint(wf.w)));

            unsigned long long xr[4];
            xr[0] = xa.x; xr[1] = xa.y; xr[2] = xb.x; xr[3] = xb.y;

            // 3) 16 independent FFMA2
            #pragma unroll
            for (int rp = 0; rp < 4; rp++)
                #pragma unroll
                for (int e = 0; e < 4; e++)
                    asm("fma.rn.f32x2 %0, %1, %2, %0;"
                        : "+l"(acc[rp][e])
                        : "l"(xr[rp]), "l"(wd[e]));

            // 4) rotate (renamed away by full unroll)
            xa = nxa; xb = nxb; wf = nwf;
        }
        __syncthreads();
    }

    // ---- epilogue ----
    float* logits_out = out;
    float* idx_out    = out + (size_t)M_TOTAL * EDIM;
    float* p_out      = idx_out + (size_t)M_TOTAL * 2;

    // rows here are UNswizzled — mainloop done, smem repurposed
    #pragma unroll
    for (int rp = 0; rp < 4; rp++) {
        #pragma unroll
        for (int e = 0; e < 4; e++) {
            unsigned int lo, hi;
            asm("mov.b64 {%0,%1}, %2;" : "=r"(lo), "=r"(hi) : "l"(acc[rp][e]));
            int r   = 8 * rg + 2 * rp;
            int col = 4 * eg + e;
            sm.ls[r][col]     = __uint_as_float(lo);
            sm.ls[r + 1][col] = __uint_as_float(hi);
        }
    }
    __syncthreads();

    // coalesced logits store: 8 x float4 per thread
    #pragma unroll
    for (int q = 0; q < 8; q++) {
        int idx = tid + NTHREADS * q;       // 0..2047 float4 slots
        int row = idx >> 4;
        int c4  = idx & 15;
        float4 v = *(const float4*)&sm.ls[row][c4 * 4];
        *(float4*)&logits_out[(size_t)(m0 + row) * EDIM + c4 * 4] = v;
    }

    // one thread per row: stable top-2 (strict >, ties -> lower index = lax.top_k)
    if (tid < BM) {
        const float* r = &sm.ls[tid][0];
        float best = -INFINITY, sec = -INFINITY;
        int bi = 0, si = 0;
        #pragma unroll 8
        for (int i = 0; i < EDIM; i++) {
            float v = r[i];
            if (v > best) { sec = best; si = bi; best = v; bi = i; }
            else if (v > sec) { sec = v; si = i; }
        }
        float tt  = expf(sec - best);
        float inv = 1.0f / (1.0f + tt);
        size_t m = (size_t)(m0 + tid);
        idx_out[m * 2 + 0] = (float)bi;
        idx_out[m * 2 + 1] = (float)si;
        p_out[m * 2 + 0]   = inv;
        p_out[m * 2 + 1]   = tt * inv;
    }
}

extern "C" void kernel_launch(void* const* d_in, const int* in_sizes, int n_in,
                              void* d_out, int out_size)
{
    const float* x  = (const float*)d_in[0];
    const float* gw = (const float*)d_in[1];
    // defensive: identify tensors by size (x = 67108864, gate_w = 262144)
    if (n_in >= 2 && in_sizes[0] < in_sizes[1]) {
        const float* tmp = x; x = gw; gw = tmp;
    }
    router_kernel<<<M_TOTAL / BM, NTHREADS>>>(x, gw, (float*)d_out);
}